// round 2
// baseline (speedup 1.0000x reference)
#include <cuda_runtime.h>
#include <math_constants.h>

#define BB 64
#define NN 64
#define TT 100

// Scratch: per-(tn, b) squared deviation. __device__ global (no allocation allowed).
static __device__ float g_nd2[TT * NN * BB];

__global__ void social_row_kernel(const float* __restrict__ x,
                                  const float* __restrict__ wfa,
                                  const int*   __restrict__ rand_idx,
                                  const int*   __restrict__ drop_mask)
{
    const int tn = blockIdx.x;          // 0 .. T*N-1, row = t*N + n
    const int b  = threadIdx.x;         // 0 .. 63 (batch element)
    const int t  = tn / NN;
    const int n  = tn - t * NN;

    // Per-batch transform: R = wfa[b,:2,:2], trans = wfa[b,:2,2]
    const float* w = wfa + b * 9;
    const float r00 = w[0], r01 = w[1], tx = w[2];
    const float r10 = w[3], r11 = w[4], ty = w[5];

    // pos = x[b, n, t, 0:2]
    const float* xp = x + (((size_t)(b * NN + n)) * TT + t) * 6;
    const float px = xp[0];
    const float py = xp[1];

    // world-frame position (einsum 'bntj,bij->bnti' + t)
    const float gx = fmaf(r00, px, r01 * py) + tx;
    const float gy = fmaf(r10, px, r11 * py) + ty;
    const float sq = fmaf(gx, gx, gy * gy);

    __shared__ float4 s[BB];
    s[b] = make_float4(gx, gy, sq, 0.0f);
    __syncthreads();

    // argmin over c of clamped d2 (sqrt is monotone; clamp applied before
    // compare; strict < keeps first occurrence like jnp.argmin)
    float mmin = CUDART_INF_F;
    int   cmin = 0;
    #pragma unroll 8
    for (int c = 0; c < BB; ++c) {
        const float4 p = s[c];
        const float d2 = (sq + p.z) - 2.0f * fmaf(gx, p.x, gy * p.y);
        float m = fmaxf(d2, 1e-12f);
        if (c == b) m = CUDART_INF_F;           // diagonal -> inf
        if (m < mmin) { mmin = m; cmin = c; }
    }

    const int idx = tn * BB + b;
    const int ri  = rand_idx[idx];
    const int rnb = ri + (ri >= b ? 1 : 0);
    const int nb  = (drop_mask[idx] != 0) ? rnb : cmin;

    const float4 p = s[nb];
    const float d2 = (sq + p.z) - 2.0f * fmaf(gx, p.x, gy * p.y);
    const float nd = sqrtf(fmaxf(d2, 1e-12f));
    const float df = nd - 1.5f;
    g_nd2[idx] = df * df;
}

__global__ void social_reduce_kernel(float* __restrict__ out)
{
    // i enumerates (n, b) with b fastest -> coalesced scratch reads
    const int i = blockIdx.x * blockDim.x + threadIdx.x;
    if (i >= BB * NN) return;
    const int b = i & (BB - 1);
    const int n = i >> 6;

    float acc = 0.0f;
    #pragma unroll 4
    for (int t = 0; t < TT; ++t)
        acc += g_nd2[(t * NN + n) * BB + b];

    out[b * NN + n] = acc * (1.0f / (float)TT);
}

extern "C" void kernel_launch(void* const* d_in, const int* in_sizes, int n_in,
                              void* d_out, int out_size)
{
    const float* x    = (const float*)d_in[0];
    const float* wfa  = (const float*)d_in[1];
    const int*   ridx = (const int*)d_in[2];
    const int*   mask = (const int*)d_in[3];
    float*       out  = (float*)d_out;

    social_row_kernel<<<TT * NN, BB>>>(x, wfa, ridx, mask);
    social_reduce_kernel<<<(BB * NN + 255) / 256, 256>>>(out);
}

// round 3
// speedup vs baseline: 1.2366x; 1.2366x over previous
#include <cuda_runtime.h>
#include <math_constants.h>

#define BB 64
#define NN 64
#define TT 100
#define CH 4                       // t-slices per block
#define NCHUNK (TT / CH)           // 25

// Partial sums over CH t's: layout [chunk][b*64 + n]  (400 KB scratch)
static __device__ float g_partial[NCHUNK * BB * NN];

__global__ __launch_bounds__(CH * BB) void social_main_kernel(
    const float* __restrict__ x,
    const float* __restrict__ wfa,
    const int*   __restrict__ rand_idx,
    const int*   __restrict__ drop_mask)
{
    const int n     = blockIdx.x;            // 0..63
    const int chunk = blockIdx.y;            // 0..24
    const int tsub  = threadIdx.x >> 6;      // 0..3
    const int b     = threadIdx.x & 63;      // 0..63
    const int t     = chunk * CH + tsub;

    __shared__ float4 s[CH][2 * BB];         // duplicated ring, 8 KB
    __shared__ float  red[CH * BB];

    // Per-batch transform
    const float* w = wfa + b * 9;
    const float r00 = w[0], r01 = w[1], tx = w[2];
    const float r10 = w[3], r11 = w[4], ty = w[5];

    // pos = x[b, n, t, 0:2]
    const float* xp = x + (((size_t)(b * NN + n)) * TT + t) * 6;
    const float px = xp[0];
    const float py = xp[1];

    const float gx = fmaf(r00, px, r01 * py) + tx;
    const float gy = fmaf(r10, px, r11 * py) + ty;
    const float sq = fmaf(gx, gx, gy * gy);

    const float4 v = make_float4(gx, gy, sq, 0.0f);
    s[tsub][b]      = v;
    s[tsub][b + BB] = v;
    __syncthreads();

    // Scan candidates c' = 1..63 (c = (b + c') & 63): diagonal skipped
    // structurally, no wrap thanks to the duplicated ring.
    // Key = clamp(sq_b + sq_c - 2*dot, 1e-12) is positive -> bit pattern is
    // order-preserving; pack rotated index into the 6 low mantissa bits and
    // argmin with a single unsigned min, 4 independent chains for ILP.
    const float4* sb   = &s[tsub][b];
    const float   m2gx = -2.0f * gx;
    const float   m2gy = -2.0f * gy;

    unsigned int ub[4] = {0xFFFFFFFFu, 0xFFFFFFFFu, 0xFFFFFFFFu, 0xFFFFFFFFu};
    #pragma unroll
    for (int cp = 1; cp < BB; ++cp) {
        const float4 p   = sb[cp];
        float key = fmaf(m2gx, p.x, fmaf(m2gy, p.y, p.z)) + sq;
        key = fmaxf(key, 1e-12f);
        const unsigned int uk = (__float_as_uint(key) & 0xFFFFFFC0u) | (unsigned int)cp;
        ub[cp & 3] = min(ub[cp & 3], uk);
    }
    const unsigned int u = min(min(ub[0], ub[1]), min(ub[2], ub[3]));
    const int cmin = (b + (int)(u & 63u)) & (BB - 1);

    const int idx = (t * NN + n) * BB + b;   // row = t*N + n, col = b
    const int ri  = rand_idx[idx];
    const int rnb = ri + (ri >= b ? 1 : 0);
    const int nb  = (drop_mask[idx] != 0) ? rnb : cmin;

    const float4 p  = s[tsub][nb];
    const float  d2 = (sq + p.z) - 2.0f * fmaf(gx, p.x, gy * p.y);
    const float  nd = sqrtf(fmaxf(d2, 1e-12f));
    const float  df = nd - 1.5f;

    red[tsub * BB + b] = df * df;
    __syncthreads();

    if (tsub == 0) {
        const float acc = red[b] + red[BB + b] + red[2 * BB + b] + red[3 * BB + b];
        g_partial[chunk * (BB * NN) + b * NN + n] = acc;
    }
}

__global__ void social_reduce_kernel(float* __restrict__ out)
{
    const int j = blockIdx.x * blockDim.x + threadIdx.x;  // 0..4095 = b*64+n
    float acc = 0.0f;
    #pragma unroll
    for (int k = 0; k < NCHUNK; ++k)
        acc += g_partial[k * (BB * NN) + j];
    out[j] = acc * (1.0f / (float)TT);
}

extern "C" void kernel_launch(void* const* d_in, const int* in_sizes, int n_in,
                              void* d_out, int out_size)
{
    const float* x    = (const float*)d_in[0];
    const float* wfa  = (const float*)d_in[1];
    const int*   ridx = (const int*)d_in[2];
    const int*   mask = (const int*)d_in[3];
    float*       out  = (float*)d_out;

    dim3 grid(NN, NCHUNK);
    social_main_kernel<<<grid, CH * BB>>>(x, wfa, ridx, mask);
    social_reduce_kernel<<<(BB * NN) / 128, 128>>>(out);
}

// round 6
// speedup vs baseline: 1.5635x; 1.2643x over previous
#include <cuda_runtime.h>
#include <math_constants.h>

#define BB 64
#define NN 64
#define TT 100
#define CH 4                       // t-slices per block
#define NCHUNK (TT / CH)           // 25

// Partials: [chunk][n][b] (400 KB, L2-resident).
static __device__ float g_partial[NCHUNK * NN * BB];

__global__ __launch_bounds__(CH * BB) void social_main_kernel(
    const float* __restrict__ x,
    const float* __restrict__ wfa,
    const int*   __restrict__ rand_idx,
    const int*   __restrict__ drop_mask)
{
    const int n     = blockIdx.x;            // 0..63
    const int chunk = blockIdx.y;            // 0..24
    const int tsub  = threadIdx.x >> 6;      // 0..3
    const int b     = threadIdx.x & 63;      // 0..63
    const int t     = chunk * CH + tsub;

    __shared__ float4 s[CH][BB];             // 4 KB
    __shared__ float  red[CH * BB];          // 1 KB

    // Per-batch transform R, trans (L1-hot across blocks)
    const float* w = wfa + b * 9;
    const float r00 = w[0], r01 = w[1], tx = w[2];
    const float r10 = w[3], r11 = w[4], ty = w[5];

    // pos = x[b, n, t, 0:2]  (8B-aligned float2: offset is a multiple of 24B)
    const float2 p2 = *(const float2*)(x + (((size_t)(b * NN + n)) * TT + t) * 6);

    const float gx = fmaf(r00, p2.x, r01 * p2.y) + tx;
    const float gy = fmaf(r10, p2.x, r11 * p2.y) + ty;
    const float sq = fmaf(gx, gx, gy * gy);

    s[tsub][b] = make_float4(gx, gy, sq, 0.0f);
    __syncthreads();

    // Broadcast scan: all lanes of a warp read the SAME candidate c
    // -> 1 smem wavefront per candidate.
    // Key = clamp(sq_b + sq_c - 2*dot, 1e-12) > 0 -> float bits are
    // order-preserving; pack candidate index into the 6 low mantissa bits,
    // unsigned-min argmin with 4 independent chains for ILP.
    // Diagonal excluded by predication (strict first-occurrence semantics
    // preserved: index packed in low bits breaks ties toward smaller c).
    const float m2gx = -2.0f * gx;
    const float m2gy = -2.0f * gy;

    unsigned int ub[4] = {0xFFFFFFFFu, 0xFFFFFFFFu, 0xFFFFFFFFu, 0xFFFFFFFFu};
    #pragma unroll
    for (int c = 0; c < BB; ++c) {
        const float4 p = s[tsub][c];
        float key = fmaf(m2gx, p.x, fmaf(m2gy, p.y, p.z)) + sq;
        key = fmaxf(key, 1e-12f);
        const unsigned int uk = (__float_as_uint(key) & 0xFFFFFFC0u) | (unsigned int)c;
        if (c != b) ub[c & 3] = min(ub[c & 3], uk);
    }
    const unsigned int u = min(min(ub[0], ub[1]), min(ub[2], ub[3]));
    const int cmin = (int)(u & 63u);

    const int idx = (t * NN + n) * BB + b;   // row = t*N + n, col = b
    const int ri  = rand_idx[idx];
    const int rnb = ri + (ri >= b ? 1 : 0);
    const int nb  = (drop_mask[idx] != 0) ? rnb : cmin;

    const float4 p  = s[tsub][nb];
    const float  d2 = (sq + p.z) - 2.0f * fmaf(gx, p.x, gy * p.y);
    const float  nd = sqrtf(fmaxf(d2, 1e-12f));
    const float  df = nd - 1.5f;

    red[tsub * BB + b] = df * df;
    __syncthreads();

    if (tsub == 0) {
        const float acc = red[b] + red[BB + b] + red[2 * BB + b] + red[3 * BB + b];
        g_partial[(chunk * NN + n) * BB + b] = acc;   // coalesced in b
    }
}

__global__ __launch_bounds__(BB) void social_reduce_kernel(float* __restrict__ out)
{
    const int n = blockIdx.x;                 // 0..63
    const int b = threadIdx.x;                // 0..63

    float acc = 0.0f;
    #pragma unroll
    for (int k = 0; k < NCHUNK; ++k)          // coalesced in b, MLP=25, L2-hot
        acc += g_partial[(k * NN + n) * BB + b];

    out[b * NN + n] = acc * (1.0f / (float)TT);
}

extern "C" void kernel_launch(void* const* d_in, const int* in_sizes, int n_in,
                              void* d_out, int out_size)
{
    const float* x    = (const float*)d_in[0];
    const float* wfa  = (const float*)d_in[1];
    const int*   ridx = (const int*)d_in[2];
    const int*   mask = (const int*)d_in[3];
    float*       out  = (float*)d_out;

    dim3 grid(NN, NCHUNK);
    social_main_kernel<<<grid, CH * BB>>>(x, wfa, ridx, mask);
    social_reduce_kernel<<<NN, BB>>>(out);
}